// round 7
// baseline (speedup 1.0000x reference)
#include <cuda_runtime.h>

#define BB 128
#define CIN 16
#define COUT 32
#define HH 32
#define WW 32
#define HOUT 30
#define WOUT 30
#define PP 900
#define KC 144            // CIN * 9
#define NELEM (BB*COUT*PP)   // 3686400
#define BO 4096           // BB*COUT

// ---------------- scratch (static __device__, no allocation) ----------------
__device__ float  g_fft[CIN*HH*WW*BB];   // [c][y][x][b]
__device__ float  g_spkt[PP*BO];         // [p][j][b]
__device__ float  g_wtt[PP*KC*COUT];     // [p][kc][o]
__device__ float  g_conv[PP*BO];         // [p][b*32+o]
__device__ float  g_rec[PP*BO];          // [p][b*32+o]
__device__ double g_part[PP*64];         // [p][ sum(32) | sumsq(32) ]
__device__ float  g_mean[COUT];
__device__ float  g_rstd[COUT];

// ---------------- kernel 1a: transpose ff [128][16384] -> [16384][128] ------
__global__ void k_transpose_ff(const float* __restrict__ ff) {
    __shared__ float t[32][33];
    int x  = blockIdx.x*32 + threadIdx.x;   // chw
    int y0 = blockIdx.y*32;                 // b
#pragma unroll
    for (int j = 0; j < 32; j += 8)
        t[threadIdx.y+j][threadIdx.x] = ff[(size_t)(y0+threadIdx.y+j)*16384 + x];
    __syncthreads();
    int xo  = blockIdx.y*32 + threadIdx.x;  // b
    int yo0 = blockIdx.x*32;
#pragma unroll
    for (int j = 0; j < 32; j += 8)
        g_fft[(size_t)(yo0+threadIdx.y+j)*128 + xo] = t[threadIdx.x][threadIdx.y+j];
}

// ---------------- kernel 1b: transpose spk [b][j][p] -> [p][j][b] -----------
__global__ void k_transpose_spk(const float* __restrict__ spk) {
    __shared__ float t[32][33];
    int jz = blockIdx.z;                    // 0..31
    int x  = blockIdx.x*32 + threadIdx.x;   // p
    int y0 = blockIdx.y*32;                 // b
#pragma unroll
    for (int j = 0; j < 32; j += 8) {
        int b = y0 + threadIdx.y + j;
        if (x < PP)
            t[threadIdx.y+j][threadIdx.x] = spk[((size_t)b*32 + jz)*PP + x];
    }
    __syncthreads();
    int bo = blockIdx.y*32 + threadIdx.x;   // b
#pragma unroll
    for (int j = 0; j < 32; j += 8) {
        int p = blockIdx.x*32 + threadIdx.y + j;
        if (p < PP)
            g_spkt[(size_t)p*BO + jz*128 + bo] = t[threadIdx.x][threadIdx.y+j];
    }
}

// ---------------- kernel 1c: weight [o][c][p][k] -> [p][c*9+k][o] -----------
__global__ void k_transform_w(const float* __restrict__ wt) {
    __shared__ float s[32*289];
    int c  = blockIdx.y;
    int p0 = blockIdx.x*32;
    for (int idx = threadIdx.x; idx < 32*288; idx += 256) {
        int o = idx / 288; int r = idx - o*288;
        int pl = r / 9;
        if (p0 + pl < PP)
            s[o*289 + r] = wt[(((size_t)o*CIN + c)*PP + p0 + pl)*9 + (r - pl*9)];
    }
    __syncthreads();
    for (int idx = threadIdx.x; idx < 288*32; idx += 256) {
        int o = idx & 31; int r = idx >> 5;
        int pl = r / 9; int k = r - pl*9;
        if (p0 + pl < PP)
            g_wtt[((size_t)(p0+pl)*KC + c*9 + k)*32 + o] = s[o*289 + r];
    }
}

// ---------------- kernel 2: per-location conv + rec GEMMs (f64 accumulate) --
// smem: s_patch 144x128 | s_wt 144x36 | s_spk 32x128 | s_lr 32x36 = 115456 B
__global__ __launch_bounds__(256, 1) void k_conv_rec(
    const float* __restrict__ lr, const float* __restrict__ bias) {
    extern __shared__ float sm[];
    float* s_patch = sm;                         // 18432 floats
    float* s_wt    = sm + 18432;                 // 5184
    float* s_spk   = sm + 18432 + 5184;          // 4096
    float* s_lr    = sm + 18432 + 5184 + 4096;   // 1152
    float* s_stage = s_patch;                    // reuse (4224 floats)

    int p = blockIdx.x;
    int h = p / 30, w = p - h*30;
    int tid = threadIdx.x;
    int oi = tid >> 5, bi = tid & 31;

    float4* sp4 = (float4*)s_patch;
    const float4* ff4 = (const float4*)g_fft;
    for (int idx = tid; idx < 144*32; idx += 256) {
        int row = idx >> 5, f4 = idx & 31;
        int c = row / 9, r9 = row - c*9;
        int y = h + r9/3, x = w + (r9 - (r9/3)*3);
        sp4[idx] = ff4[(size_t)((c*32 + y)*32 + x)*32 + f4];
    }
    float4* sw4 = (float4*)s_wt;
    const float4* wt4 = (const float4*)g_wtt;
    for (int idx = tid; idx < 1152; idx += 256) {
        int row = idx >> 3, f4 = idx & 7;
        sw4[row*9 + f4] = wt4[(size_t)p*1152 + idx];
    }
    float4* ss4 = (float4*)s_spk;
    const float4* sk4 = (const float4*)g_spkt;
    for (int idx = tid; idx < 1024; idx += 256)
        ss4[idx] = sk4[(size_t)p*1024 + idx];
    for (int idx = tid; idx < 1024; idx += 256)
        s_lr[(idx & 31)*36 + (idx >> 5)] = lr[(size_t)p*1024 + idx];
    __syncthreads();

    // ---- conv GEMM in f64: accd[j][i] = out(o=4*oi+j, b=4*bi+i) ----
    // f32*f32 products are exact in f64; the 144-term f64 sum is exact to
    // 2^-53, i.e. the true dot product regardless of XLA's reduction order.
    double accd[4][4] = {};
#pragma unroll 2
    for (int kk = 0; kk < 144; kk++) {
        float4 pv = sp4[kk*32 + bi];
        float4 wv = sw4[kk*9 + oi];
        double px = pv.x, py = pv.y, pz = pv.z, pw = pv.w;
        double wx = wv.x, wy = wv.y, wz = wv.z, ww = wv.w;
        accd[0][0] = fma(px,wx,accd[0][0]); accd[0][1] = fma(py,wx,accd[0][1]);
        accd[0][2] = fma(pz,wx,accd[0][2]); accd[0][3] = fma(pw,wx,accd[0][3]);
        accd[1][0] = fma(px,wy,accd[1][0]); accd[1][1] = fma(py,wy,accd[1][1]);
        accd[1][2] = fma(pz,wy,accd[1][2]); accd[1][3] = fma(pw,wy,accd[1][3]);
        accd[2][0] = fma(px,wz,accd[2][0]); accd[2][1] = fma(py,wz,accd[2][1]);
        accd[2][2] = fma(pz,wz,accd[2][2]); accd[2][3] = fma(pw,wz,accd[2][3]);
        accd[3][0] = fma(px,ww,accd[3][0]); accd[3][1] = fma(py,ww,accd[3][1]);
        accd[3][2] = fma(pz,ww,accd[3][2]); accd[3][3] = fma(pw,ww,accd[3][3]);
    }
    float acc[4][4];
#pragma unroll
    for (int j = 0; j < 4; j++) {
        float bv = bias[(4*oi + j)*PP + p];
#pragma unroll
        for (int i = 0; i < 4; i++)
            acc[j][i] = __fadd_rn((float)accd[j][i], bv);
    }
    // ---- BN partial sums over the f32-rounded conv values (f64, exact) ----
    double ps[4], pq[4];
#pragma unroll
    for (int j = 0; j < 4; j++) {
        double a0 = acc[j][0], a1 = acc[j][1], a2 = acc[j][2], a3 = acc[j][3];
        ps[j] = (a0 + a1) + (a2 + a3);
        pq[j] = (a0*a0 + a1*a1) + (a2*a2 + a3*a3);
    }
#pragma unroll
    for (int off = 16; off > 0; off >>= 1) {
#pragma unroll
        for (int j = 0; j < 4; j++) {
            ps[j] += __shfl_down_sync(0xffffffffu, ps[j], off);
            pq[j] += __shfl_down_sync(0xffffffffu, pq[j], off);
        }
    }
    if (bi == 0) {
#pragma unroll
        for (int j = 0; j < 4; j++) {
            g_part[p*64 + 4*oi + j]      = ps[j];
            g_part[p*64 + 32 + 4*oi + j] = pq[j];
        }
    }
    __syncthreads();                         // s_patch dead, reuse as stage
#pragma unroll
    for (int i = 0; i < 4; i++)
#pragma unroll
        for (int j = 0; j < 4; j++)
            s_stage[(4*bi + i)*33 + 4*oi + j] = acc[j][i];
    __syncthreads();
    for (int idx = tid; idx < 4096; idx += 256)
        g_conv[(size_t)p*BO + idx] = s_stage[(idx >> 5)*33 + (idx & 31)];

    // ---- rec GEMM in f64: rec[b][i] = sum_j lr[p][i][j] * spk[b][j][p] ----
#pragma unroll
    for (int j = 0; j < 4; j++)
#pragma unroll
        for (int i = 0; i < 4; i++) accd[j][i] = 0.0;
#pragma unroll 2
    for (int jj = 0; jj < 32; jj++) {
        float4 pv = ss4[jj*32 + bi];
        float4 lv = ((float4*)s_lr)[jj*9 + oi];
        double px = pv.x, py = pv.y, pz = pv.z, pw = pv.w;
        double wx = lv.x, wy = lv.y, wz = lv.z, ww = lv.w;
        accd[0][0] = fma(px,wx,accd[0][0]); accd[0][1] = fma(py,wx,accd[0][1]);
        accd[0][2] = fma(pz,wx,accd[0][2]); accd[0][3] = fma(pw,wx,accd[0][3]);
        accd[1][0] = fma(px,wy,accd[1][0]); accd[1][1] = fma(py,wy,accd[1][1]);
        accd[1][2] = fma(pz,wy,accd[1][2]); accd[1][3] = fma(pw,wy,accd[1][3]);
        accd[2][0] = fma(px,wz,accd[2][0]); accd[2][1] = fma(py,wz,accd[2][1]);
        accd[2][2] = fma(pz,wz,accd[2][2]); accd[2][3] = fma(pw,wz,accd[2][3]);
        accd[3][0] = fma(px,ww,accd[3][0]); accd[3][1] = fma(py,ww,accd[3][1]);
        accd[3][2] = fma(pz,ww,accd[3][2]); accd[3][3] = fma(pw,ww,accd[3][3]);
    }
    __syncthreads();                         // conv write loop done w/ s_stage
#pragma unroll
    for (int i = 0; i < 4; i++)
#pragma unroll
        for (int j = 0; j < 4; j++)
            s_stage[(4*bi + i)*33 + 4*oi + j] = (float)accd[j][i];
    __syncthreads();
    for (int idx = tid; idx < 4096; idx += 256)
        g_rec[(size_t)p*BO + idx] = s_stage[(idx >> 5)*33 + (idx & 31)];
}

// ---------------- kernel 3: finalize BN stats (double ~= exact) -------------
__global__ void k_stats() {
    __shared__ double sred[16][65];
    int tid = threadIdx.x;          // 1024 threads
    int col = tid & 63, seg = tid >> 6;
    double acc = 0.0;
    for (int p = seg; p < PP; p += 16)
        acc += g_part[p*64 + col];
    sred[seg][col] = acc;
    __syncthreads();
    if (tid < 64) {
        double s = 0.0;
#pragma unroll
        for (int i = 0; i < 16; i++) s += sred[i][tid];
        sred[0][tid] = s;
    }
    __syncthreads();
    if (tid < 32) {
        double sum   = sred[0][tid];
        double sumsq = sred[0][tid + 32];
        double mean_d = sum / 115200.0;
        float  mean_f = (float)mean_d;
        // E[(x - mean_f)^2] exactly in double, given the f32-rounded mean
        double var = sumsq / 115200.0
                   - 2.0 * (double)mean_f * mean_d
                   + (double)mean_f * (double)mean_f;
        float vf = (float)var;
        g_mean[tid] = mean_f;
        g_rstd[tid] = rsqrtf(__fadd_rn(vf, 1e-5f));
    }
}

// ---------------- kernel 4: fused BN-apply + rec-add + LIF ------------------
// f32 elementwise chain mirrors the reference formula order op-for-op.
__global__ __launch_bounds__(256) void k_final(
    const float* __restrict__ fb, const float* __restrict__ soma,
    const float* __restrict__ spk, const float* __restrict__ ac,
    const float* __restrict__ bt,
    const float* __restrict__ gamma, const float* __restrict__ beta,
    const float* __restrict__ tau_m, const float* __restrict__ tau_adp,
    const float* __restrict__ tau_a, float* __restrict__ out) {
    __shared__ float s_conv[60*65];
    __shared__ float s_rec[60*65];
    __shared__ float s_mean[COUT], s_rstd[COUT], s_g[COUT], s_b[COUT];
    int bo0 = blockIdx.x * 64;
    int p0  = blockIdx.y * 60;
    int tid = threadIdx.x;
    if (tid < COUT) {
        s_mean[tid] = g_mean[tid];
        s_rstd[tid] = g_rstd[tid];
        s_g[tid]    = gamma[tid];
        s_b[tid]    = beta[tid];
    }
    for (int idx = tid; idx < 60*64; idx += 256) {
        int r = idx >> 6, c = idx & 63;
        s_conv[r*65 + c] = g_conv[(size_t)(p0 + r)*BO + bo0 + c];
        s_rec [r*65 + c] = g_rec [(size_t)(p0 + r)*BO + bo0 + c];
    }
    __syncthreads();
    for (int idx = tid; idx < 64*60; idx += 256) {
        int bol = idx / 60, pl = idx - bol*60;
        int bo = bo0 + bol;
        int o = bo & 31;
        size_t g = (size_t)bo*PP + p0 + pl;
        int tix = o*PP + p0 + pl;
        // alpha/rho/eta exactly as reference: exp(-0.5f / tau), libdevice expf
        float alpha = expf(__fdiv_rn(-0.5f, tau_m[tix]));
        float rho   = expf(__fdiv_rn(-0.5f, tau_adp[tix]));
        float eta   = expf(__fdiv_rn(-0.5f, tau_a[tix]));
        float sv = spk[g];
        // b_new = rho*b + (1-rho)*spk
        float bn = __fadd_rn(__fmul_rn(rho, bt[g]),
                             __fmul_rn(__fsub_rn(1.0f, rho), sv));
        // thr = 0.1 + 1.8*b_new
        float thr = __fadd_rn(0.1f, __fmul_rn(1.8f, bn));
        // a_new = eta*a + fb
        float an = __fadd_rn(__fmul_rn(eta, ac[g]), fb[g]);
        // sigmoid(a_new) = 1 / (1 + exp(-a_new))
        float sig = __fdiv_rn(1.0f, __fadd_rn(1.0f, expf(-an)));
        // BN in reference order: x=(conv-mean)*rstd; cx=x*gamma+beta; cx+=rec
        float cv = s_conv[pl*65 + bol];
        float xn = __fmul_rn(__fsub_rn(cv, s_mean[o]), s_rstd[o]);
        float cx = __fadd_rn(__fmul_rn(xn, s_g[o]), s_b[o]);
        cx = __fadd_rn(cx, s_rec[pl*65 + bol]);
        // soma_new = ((alpha*soma + (sig-0.5)) + cx) - thr*spk
        float t  = __fadd_rn(__fmul_rn(alpha, soma[g]), __fsub_rn(sig, 0.5f));
        t = __fadd_rn(t, cx);
        float sn = __fsub_rn(t, __fmul_rn(thr, sv));
        float spike = (__fsub_rn(sn, thr) > 0.0f) ? 1.0f : 0.0f;
        out[g]            = sn;
        out[NELEM + g]    = spike;
        out[2*NELEM + g]  = an;
        out[3*NELEM + g]  = bn;
    }
}

// ---------------------------------------------------------------------------
extern "C" void kernel_launch(void* const* d_in, const int* in_sizes, int n_in,
                              void* d_out, int out_size) {
    const float* ff      = (const float*)d_in[0];
    const float* fb      = (const float*)d_in[1];
    const float* soma    = (const float*)d_in[2];
    const float* spk     = (const float*)d_in[3];
    const float* ac      = (const float*)d_in[4];
    const float* bt      = (const float*)d_in[5];
    const float* wt      = (const float*)d_in[6];
    const float* bias    = (const float*)d_in[7];
    const float* lr      = (const float*)d_in[8];
    const float* gamma   = (const float*)d_in[9];
    const float* beta    = (const float*)d_in[10];
    const float* tau_m   = (const float*)d_in[11];
    const float* tau_adp = (const float*)d_in[12];
    const float* tau_a   = (const float*)d_in[13];
    float* out = (float*)d_out;

    k_transpose_ff <<<dim3(512, 4),     dim3(32, 8)>>>(ff);
    k_transpose_spk<<<dim3(29, 4, 32),  dim3(32, 8)>>>(spk);
    k_transform_w  <<<dim3(29, 16),     256>>>(wt);

    const int smem2 = 115456;
    cudaFuncSetAttribute(k_conv_rec, cudaFuncAttributeMaxDynamicSharedMemorySize, smem2);
    k_conv_rec<<<900, 256, smem2>>>(lr, bias);

    k_stats<<<1, 1024>>>();
    k_final<<<dim3(64, 15), 256>>>(fb, soma, spk, ac, bt, gamma, beta,
                                   tau_m, tau_adp, tau_a, out);
}

// round 8
// speedup vs baseline: 1.0263x; 1.0263x over previous
#include <cuda_runtime.h>

#define BB 128
#define CIN 16
#define COUT 32
#define HH 32
#define WW 32
#define HOUT 30
#define WOUT 30
#define PP 900
#define KC 144            // CIN * 9
#define NELEM (BB*COUT*PP)   // 3686400
#define BO 4096           // BB*COUT
#define FIXCAP (1<<20)
#define MARGIN_TAU 2e-3f

// ---------------- scratch (static __device__, no allocation) ----------------
__device__ float  g_fft[CIN*HH*WW*BB];   // [c][y][x][b]
__device__ float  g_spkt[PP*BO];         // [p][j][b]
__device__ float  g_wtt[PP*KC*COUT];     // [p][kc][o]
__device__ float  g_conv[PP*BO];         // [p][b*32+o]
__device__ float  g_rec[PP*BO];          // [p][b*32+o]
__device__ double g_part[PP*64];         // [p][ sum(32) | sumsq(32) ]
__device__ float  g_mean[COUT];
__device__ float  g_rstd[COUT];
__device__ int    g_fix_cnt;
__device__ int    g_fix_list[FIXCAP];

// ---------------- kernel 1a: transpose ff [128][16384] -> [16384][128] ------
__global__ void k_transpose_ff(const float* __restrict__ ff) {
    __shared__ float t[32][33];
    int x  = blockIdx.x*32 + threadIdx.x;   // chw
    int y0 = blockIdx.y*32;                 // b
#pragma unroll
    for (int j = 0; j < 32; j += 8)
        t[threadIdx.y+j][threadIdx.x] = ff[(size_t)(y0+threadIdx.y+j)*16384 + x];
    __syncthreads();
    int xo  = blockIdx.y*32 + threadIdx.x;  // b
    int yo0 = blockIdx.x*32;
#pragma unroll
    for (int j = 0; j < 32; j += 8)
        g_fft[(size_t)(yo0+threadIdx.y+j)*128 + xo] = t[threadIdx.x][threadIdx.y+j];
}

// ---------------- kernel 1b: transpose spk [b][j][p] -> [p][j][b] -----------
__global__ void k_transpose_spk(const float* __restrict__ spk) {
    __shared__ float t[32][33];
    int jz = blockIdx.z;                    // 0..31
    int x  = blockIdx.x*32 + threadIdx.x;   // p
    int y0 = blockIdx.y*32;                 // b
#pragma unroll
    for (int j = 0; j < 32; j += 8) {
        int b = y0 + threadIdx.y + j;
        if (x < PP)
            t[threadIdx.y+j][threadIdx.x] = spk[((size_t)b*32 + jz)*PP + x];
    }
    __syncthreads();
    int bo = blockIdx.y*32 + threadIdx.x;   // b
#pragma unroll
    for (int j = 0; j < 32; j += 8) {
        int p = blockIdx.x*32 + threadIdx.y + j;
        if (p < PP)
            g_spkt[(size_t)p*BO + jz*128 + bo] = t[threadIdx.x][threadIdx.y+j];
    }
}

// ---------------- kernel 1c: weight [o][c][p][k] -> [p][c*9+k][o] -----------
__global__ void k_transform_w(const float* __restrict__ wt) {
    __shared__ float s[32*289];
    int c  = blockIdx.y;
    int p0 = blockIdx.x*32;
    for (int idx = threadIdx.x; idx < 32*288; idx += 256) {
        int o = idx / 288; int r = idx - o*288;
        int pl = r / 9;
        if (p0 + pl < PP)
            s[o*289 + r] = wt[(((size_t)o*CIN + c)*PP + p0 + pl)*9 + (r - pl*9)];
    }
    __syncthreads();
    for (int idx = threadIdx.x; idx < 288*32; idx += 256) {
        int o = idx & 31; int r = idx >> 5;
        int pl = r / 9; int k = r - pl*9;
        if (p0 + pl < PP)
            g_wtt[((size_t)(p0+pl)*KC + c*9 + k)*32 + o] = s[o*289 + r];
    }
}

// ---------------- kernel 2: per-location conv + rec GEMMs (f32, fast path) --
// smem: s_patch 144x128 | s_wt 144x36 | s_spk 32x128 | s_lr 32x36 = 115456 B
__global__ __launch_bounds__(256, 2) void k_conv_rec(
    const float* __restrict__ lr, const float* __restrict__ bias) {
    extern __shared__ float sm[];
    float* s_patch = sm;                         // 18432 floats
    float* s_wt    = sm + 18432;                 // 5184
    float* s_spk   = sm + 18432 + 5184;          // 4096
    float* s_lr    = sm + 18432 + 5184 + 4096;   // 1152
    float* s_stage = s_patch;                    // reuse (4224 floats)

    int p = blockIdx.x;
    int h = p / 30, w = p - h*30;
    int tid = threadIdx.x;
    int oi = tid >> 5, bi = tid & 31;

    float4* sp4 = (float4*)s_patch;
    const float4* ff4 = (const float4*)g_fft;
    for (int idx = tid; idx < 144*32; idx += 256) {
        int row = idx >> 5, f4 = idx & 31;
        int c = row / 9, r9 = row - c*9;
        int y = h + r9/3, x = w + (r9 - (r9/3)*3);
        sp4[idx] = ff4[(size_t)((c*32 + y)*32 + x)*32 + f4];
    }
    float4* sw4 = (float4*)s_wt;
    const float4* wt4 = (const float4*)g_wtt;
    for (int idx = tid; idx < 1152; idx += 256) {
        int row = idx >> 3, f4 = idx & 7;
        sw4[row*9 + f4] = wt4[(size_t)p*1152 + idx];
    }
    float4* ss4 = (float4*)s_spk;
    const float4* sk4 = (const float4*)g_spkt;
    for (int idx = tid; idx < 1024; idx += 256)
        ss4[idx] = sk4[(size_t)p*1024 + idx];
    for (int idx = tid; idx < 1024; idx += 256)
        s_lr[(idx & 31)*36 + (idx >> 5)] = lr[(size_t)p*1024 + idx];
    __syncthreads();

    // ---- conv GEMM (f32): acc[j][i] = out(o=4*oi+j, b=4*bi+i) ----
    float acc[4][4] = {};
#pragma unroll 4
    for (int kk = 0; kk < 144; kk++) {
        float4 pv = sp4[kk*32 + bi];
        float4 wv = sw4[kk*9 + oi];
        acc[0][0] += pv.x*wv.x; acc[0][1] += pv.y*wv.x; acc[0][2] += pv.z*wv.x; acc[0][3] += pv.w*wv.x;
        acc[1][0] += pv.x*wv.y; acc[1][1] += pv.y*wv.y; acc[1][2] += pv.z*wv.y; acc[1][3] += pv.w*wv.y;
        acc[2][0] += pv.x*wv.z; acc[2][1] += pv.y*wv.z; acc[2][2] += pv.z*wv.z; acc[2][3] += pv.w*wv.z;
        acc[3][0] += pv.x*wv.w; acc[3][1] += pv.y*wv.w; acc[3][2] += pv.z*wv.w; acc[3][3] += pv.w*wv.w;
    }
#pragma unroll
    for (int j = 0; j < 4; j++) {
        float bv = bias[(4*oi + j)*PP + p];
#pragma unroll
        for (int i = 0; i < 4; i++) acc[j][i] = __fadd_rn(acc[j][i], bv);
    }
    // ---- BN partial sums over f32 conv values (f64, deterministic) ----
    double ps[4], pq[4];
#pragma unroll
    for (int j = 0; j < 4; j++) {
        double a0 = acc[j][0], a1 = acc[j][1], a2 = acc[j][2], a3 = acc[j][3];
        ps[j] = (a0 + a1) + (a2 + a3);
        pq[j] = (a0*a0 + a1*a1) + (a2*a2 + a3*a3);
    }
#pragma unroll
    for (int off = 16; off > 0; off >>= 1) {
#pragma unroll
        for (int j = 0; j < 4; j++) {
            ps[j] += __shfl_down_sync(0xffffffffu, ps[j], off);
            pq[j] += __shfl_down_sync(0xffffffffu, pq[j], off);
        }
    }
    if (bi == 0) {
#pragma unroll
        for (int j = 0; j < 4; j++) {
            g_part[p*64 + 4*oi + j]      = ps[j];
            g_part[p*64 + 32 + 4*oi + j] = pq[j];
        }
    }
    __syncthreads();                         // s_patch dead, reuse as stage
#pragma unroll
    for (int i = 0; i < 4; i++)
#pragma unroll
        for (int j = 0; j < 4; j++)
            s_stage[(4*bi + i)*33 + 4*oi + j] = acc[j][i];
    __syncthreads();
    for (int idx = tid; idx < 4096; idx += 256)
        g_conv[(size_t)p*BO + idx] = s_stage[(idx >> 5)*33 + (idx & 31)];

    // ---- rec GEMM (f32): rec[b][i] = sum_j lr[p][i][j] * spk[b][j][p] ----
#pragma unroll
    for (int j = 0; j < 4; j++)
#pragma unroll
        for (int i = 0; i < 4; i++) acc[j][i] = 0.f;
#pragma unroll 4
    for (int jj = 0; jj < 32; jj++) {
        float4 pv = ss4[jj*32 + bi];
        float4 lv = ((float4*)s_lr)[jj*9 + oi];
        acc[0][0] += pv.x*lv.x; acc[0][1] += pv.y*lv.x; acc[0][2] += pv.z*lv.x; acc[0][3] += pv.w*lv.x;
        acc[1][0] += pv.x*lv.y; acc[1][1] += pv.y*lv.y; acc[1][2] += pv.z*lv.y; acc[1][3] += pv.w*lv.y;
        acc[2][0] += pv.x*lv.z; acc[2][1] += pv.y*lv.z; acc[2][2] += pv.z*lv.z; acc[2][3] += pv.w*lv.z;
        acc[3][0] += pv.x*lv.w; acc[3][1] += pv.y*lv.w; acc[3][2] += pv.z*lv.w; acc[3][3] += pv.w*lv.w;
    }
    __syncthreads();                         // conv write loop done w/ s_stage
#pragma unroll
    for (int i = 0; i < 4; i++)
#pragma unroll
        for (int j = 0; j < 4; j++)
            s_stage[(4*bi + i)*33 + 4*oi + j] = acc[j][i];
    __syncthreads();
    for (int idx = tid; idx < 4096; idx += 256)
        g_rec[(size_t)p*BO + idx] = s_stage[(idx >> 5)*33 + (idx & 31)];
}

// ---------------- kernel 3: finalize BN stats (double ~= exact) -------------
__global__ void k_stats() {
    __shared__ double sred[16][65];
    int tid = threadIdx.x;          // 1024 threads
    int col = tid & 63, seg = tid >> 6;
    if (tid == 0) g_fix_cnt = 0;    // reset fixup list for this launch
    double acc = 0.0;
    for (int p = seg; p < PP; p += 16)
        acc += g_part[p*64 + col];
    sred[seg][col] = acc;
    __syncthreads();
    if (tid < 64) {
        double s = 0.0;
#pragma unroll
        for (int i = 0; i < 16; i++) s += sred[i][tid];
        sred[0][tid] = s;
    }
    __syncthreads();
    if (tid < 32) {
        double sum   = sred[0][tid];
        double sumsq = sred[0][tid + 32];
        double mean_d = sum / 115200.0;
        float  mean_f = (float)mean_d;
        double var = sumsq / 115200.0
                   - 2.0 * (double)mean_f * mean_d
                   + (double)mean_f * (double)mean_f;
        float vf = (float)var;
        g_mean[tid] = mean_f;
        g_rstd[tid] = rsqrtf(__fadd_rn(vf, 1e-5f));
    }
}

// ---- shared elementwise chain (reference op order, _rn to forbid fusion) ---
__device__ __forceinline__ void lif_chain(
    float cv, float rec, float sv, float btv, float acv, float fbv, float somav,
    float tm, float tadp, float ta, float mean, float rstd, float gm, float bt_,
    float& sn, float& spike, float& an, float& bn)
{
    float alpha = expf(__fdiv_rn(-0.5f, tm));
    float rho   = expf(__fdiv_rn(-0.5f, tadp));
    float eta   = expf(__fdiv_rn(-0.5f, ta));
    bn = __fadd_rn(__fmul_rn(rho, btv), __fmul_rn(__fsub_rn(1.0f, rho), sv));
    float thr = __fadd_rn(0.1f, __fmul_rn(1.8f, bn));
    an = __fadd_rn(__fmul_rn(eta, acv), fbv);
    float sig = __fdiv_rn(1.0f, __fadd_rn(1.0f, expf(-an)));
    float xn = __fmul_rn(__fsub_rn(cv, mean), rstd);
    float cx = __fadd_rn(__fmul_rn(xn, gm), bt_);
    cx = __fadd_rn(cx, rec);
    float t  = __fadd_rn(__fmul_rn(alpha, somav), __fsub_rn(sig, 0.5f));
    t = __fadd_rn(t, cx);
    sn = __fsub_rn(t, __fmul_rn(thr, sv));
    spike = (__fsub_rn(sn, thr) > 0.0f) ? 1.0f : 0.0f;
}

// ---------------- kernel 4: fused BN-apply + rec-add + LIF + margin flag ----
__global__ __launch_bounds__(256) void k_final(
    const float* __restrict__ fb, const float* __restrict__ soma,
    const float* __restrict__ spk, const float* __restrict__ ac,
    const float* __restrict__ bt,
    const float* __restrict__ gamma, const float* __restrict__ beta,
    const float* __restrict__ tau_m, const float* __restrict__ tau_adp,
    const float* __restrict__ tau_a, float* __restrict__ out) {
    __shared__ float s_conv[60*65];
    __shared__ float s_rec[60*65];
    __shared__ float s_mean[COUT], s_rstd[COUT], s_g[COUT], s_b[COUT];
    int bo0 = blockIdx.x * 64;
    int p0  = blockIdx.y * 60;
    int tid = threadIdx.x;
    if (tid < COUT) {
        s_mean[tid] = g_mean[tid];
        s_rstd[tid] = g_rstd[tid];
        s_g[tid]    = gamma[tid];
        s_b[tid]    = beta[tid];
    }
    for (int idx = tid; idx < 60*64; idx += 256) {
        int r = idx >> 6, c = idx & 63;
        s_conv[r*65 + c] = g_conv[(size_t)(p0 + r)*BO + bo0 + c];
        s_rec [r*65 + c] = g_rec [(size_t)(p0 + r)*BO + bo0 + c];
    }
    __syncthreads();
    for (int idx = tid; idx < 64*60; idx += 256) {
        int bol = idx / 60, pl = idx - bol*60;
        int bo = bo0 + bol;
        int o = bo & 31;
        size_t g = (size_t)bo*PP + p0 + pl;
        int tix = o*PP + p0 + pl;
        float sv = spk[g];
        float sn, spike, an, bn;
        lif_chain(s_conv[pl*65 + bol], s_rec[pl*65 + bol], sv,
                  bt[g], ac[g], fb[g], soma[g],
                  tau_m[tix], tau_adp[tix], tau_a[tix],
                  s_mean[o], s_rstd[o], s_g[o], s_b[o],
                  sn, spike, an, bn);
        out[g]            = sn;
        out[NELEM + g]    = spike;
        out[2*NELEM + g]  = an;
        out[3*NELEM + g]  = bn;
        // flag knife-edge elements for exact recompute
        float thr = __fadd_rn(0.1f, __fmul_rn(1.8f, bn));
        if (fabsf(__fsub_rn(sn, thr)) < MARGIN_TAU) {
            int slot = atomicAdd(&g_fix_cnt, 1);
            if (slot < FIXCAP) g_fix_list[slot] = (int)g;
        }
    }
}

// ---------------- kernel 5: exact f64 recompute of flagged elements ---------
__global__ __launch_bounds__(256) void k_fixup(
    const float* __restrict__ lr, const float* __restrict__ bias,
    const float* __restrict__ fb, const float* __restrict__ soma,
    const float* __restrict__ spk, const float* __restrict__ ac,
    const float* __restrict__ bt,
    const float* __restrict__ gamma, const float* __restrict__ beta,
    const float* __restrict__ tau_m, const float* __restrict__ tau_adp,
    const float* __restrict__ tau_a, float* __restrict__ out) {
    int n = g_fix_cnt;
    if (n > FIXCAP) n = FIXCAP;
    int lane = threadIdx.x & 31;
    int wglob = (blockIdx.x * blockDim.x + threadIdx.x) >> 5;
    int nw = (gridDim.x * blockDim.x) >> 5;
    for (int e = wglob; e < n; e += nw) {
        int g = g_fix_list[e];
        int p  = g % PP;
        int bo = g / PP;
        int o = bo & 31, b = bo >> 5;
        int h = p / 30, w0 = p - h*30;
        // exact conv dot: 144 terms, f64, deterministic xor tree
        double acc = 0.0;
        for (int k = lane; k < 144; k += 32) {
            int c = k / 9, r = k - c*9;
            int y = h + r/3, x = w0 + (r - (r/3)*3);
            double pv = (double)g_fft[(size_t)((c*32 + y)*32 + x)*128 + b];
            double wv = (double)g_wtt[((size_t)p*KC + k)*32 + o];
            acc = fma(pv, wv, acc);
        }
#pragma unroll
        for (int off = 16; off > 0; off >>= 1)
            acc += __shfl_xor_sync(0xffffffffu, acc, off);
        // exact rec dot: 32 terms (one per lane)
        double lv = (double)lr[(size_t)p*1024 + o*32 + lane];
        double sj = (double)spk[((size_t)b*32 + lane)*PP + p];
        double racc = lv * sj;
#pragma unroll
        for (int off = 16; off > 0; off >>= 1)
            racc += __shfl_xor_sync(0xffffffffu, racc, off);
        if (lane == 0) {
            float cv  = __fadd_rn((float)acc, bias[o*PP + p]);
            float rec = (float)racc;
            int tix = o*PP + p;
            float sv = spk[g];
            float sn, spike, an, bn;
            lif_chain(cv, rec, sv, bt[g], ac[g], fb[g], soma[g],
                      tau_m[tix], tau_adp[tix], tau_a[tix],
                      g_mean[o], g_rstd[o], gamma[o], beta[o],
                      sn, spike, an, bn);
            out[g]            = sn;
            out[NELEM + g]    = spike;
            out[2*NELEM + g]  = an;
            out[3*NELEM + g]  = bn;
        }
    }
}

// ---------------------------------------------------------------------------
extern "C" void kernel_launch(void* const* d_in, const int* in_sizes, int n_in,
                              void* d_out, int out_size) {
    const float* ff      = (const float*)d_in[0];
    const float* fb      = (const float*)d_in[1];
    const float* soma    = (const float*)d_in[2];
    const float* spk     = (const float*)d_in[3];
    const float* ac      = (const float*)d_in[4];
    const float* bt      = (const float*)d_in[5];
    const float* wt      = (const float*)d_in[6];
    const float* bias    = (const float*)d_in[7];
    const float* lr      = (const float*)d_in[8];
    const float* gamma   = (const float*)d_in[9];
    const float* beta    = (const float*)d_in[10];
    const float* tau_m   = (const float*)d_in[11];
    const float* tau_adp = (const float*)d_in[12];
    const float* tau_a   = (const float*)d_in[13];
    float* out = (float*)d_out;

    k_transpose_ff <<<dim3(512, 4),     dim3(32, 8)>>>(ff);
    k_transpose_spk<<<dim3(29, 4, 32),  dim3(32, 8)>>>(spk);
    k_transform_w  <<<dim3(29, 16),     256>>>(wt);

    const int smem2 = 115456;
    cudaFuncSetAttribute(k_conv_rec, cudaFuncAttributeMaxDynamicSharedMemorySize, smem2);
    k_conv_rec<<<900, 256, smem2>>>(lr, bias);

    k_stats<<<1, 1024>>>();
    k_final<<<dim3(64, 15), 256>>>(fb, soma, spk, ac, bt, gamma, beta,
                                   tau_m, tau_adp, tau_a, out);
    k_fixup<<<148, 256>>>(lr, bias, fb, soma, spk, ac, bt, gamma, beta,
                          tau_m, tau_adp, tau_a, out);
}